// round 6
// baseline (speedup 1.0000x reference)
#include <cuda_runtime.h>

#define NPTS   100000
#define BATCH  4096
#define KSEL   10
#define TPB    32
#define RPB    2                      // rays per block (= per warp)
#define GRID   (BATCH / RPB)          // 2048 blocks
#define UNR    4
#define NCHUNK (NPTS / (32 * UNR))    // 781, tail = 32 points

__device__ float4 g_packed[NPTS];     // (-2x, -2y, -2z, |x|^2)

__global__ __launch_bounds__(256)
void pack_kernel(const float* __restrict__ xyz)
{
    int i = blockIdx.x * 256 + threadIdx.x;
    if (i < NPTS) {
        float x = xyz[i * 3 + 0];
        float y = xyz[i * 3 + 1];
        float z = xyz[i * 3 + 2];
        float q = fmaf(x, x, fmaf(y, y, z * z));
        g_packed[i] = make_float4(-2.0f * x, -2.0f * y, -2.0f * z, q);
    }
}

__global__ __launch_bounds__(TPB)
void gs_topk_kernel(const float* __restrict__ rays_o,
                    const float* __restrict__ rays_d,
                    const float* __restrict__ fdc,
                    const float* __restrict__ opac,
                    float* __restrict__ out)
{
    __shared__ float md2 [RPB * 32 * KSEL];   // 2.5 KB
    __shared__ int   midx[RPB * 32 * KSEL];   // 2.5 KB
    __shared__ float sT[RPB];
    volatile float* sTv = sT;

    const int lane    = threadIdx.x;
    const int rayBase = blockIdx.x * RPB;

    // Ray constants for the two rays this warp owns
    float ax, ay, az, CA, bx, by, bz, CB;
    {
        int rA = rayBase + 0, rB = rayBase + 1;
        ax = fmaf(3.0f, rays_d[rA * 3 + 0], rays_o[rA * 3 + 0]);
        ay = fmaf(3.0f, rays_d[rA * 3 + 1], rays_o[rA * 3 + 1]);
        az = fmaf(3.0f, rays_d[rA * 3 + 2], rays_o[rA * 3 + 2]);
        CA = ax * ax + ay * ay + az * az;
        bx = fmaf(3.0f, rays_d[rB * 3 + 0], rays_o[rB * 3 + 0]);
        by = fmaf(3.0f, rays_d[rB * 3 + 1], rays_o[rB * 3 + 1]);
        bz = fmaf(3.0f, rays_d[rB * 3 + 2], rays_o[rB * 3 + 2]);
        CB = bx * bx + by * by + bz * bz;
    }
    if (lane < RPB) sT[lane] = 3.0e38f;
    __syncthreads();

    // Per-lane sorted (ascending) top-K per ray, s-domain (s = d^2 - C)
    float bestA[KSEL], bestB[KSEL];
    int   idxA[KSEL],  idxB[KSEL];
#pragma unroll
    for (int j = 0; j < KSEL; j++) {
        bestA[j] = 3.0e38f; idxA[j] = 0;
        bestB[j] = 3.0e38f; idxB[j] = 0;
    }
    float tlA = 3.0e38f, tlB = 3.0e38f;

    const float4* p = g_packed + lane;
    int pbase = lane;

#pragma unroll 1
    for (int c = 0; c < NCHUNK; c++) {
        float TA = fminf(sTv[0], tlA);
        float TB = fminf(sTv[1], tlB);
        float4 q0 = p[0 * 32];
        float4 q1 = p[1 * 32];
        float4 q2 = p[2 * 32];
        float4 q3 = p[3 * 32];
        float sA0 = fmaf(ax, q0.x, fmaf(ay, q0.y, fmaf(az, q0.z, q0.w)));
        float sA1 = fmaf(ax, q1.x, fmaf(ay, q1.y, fmaf(az, q1.z, q1.w)));
        float sA2 = fmaf(ax, q2.x, fmaf(ay, q2.y, fmaf(az, q2.z, q2.w)));
        float sA3 = fmaf(ax, q3.x, fmaf(ay, q3.y, fmaf(az, q3.z, q3.w)));
        float sB0 = fmaf(bx, q0.x, fmaf(by, q0.y, fmaf(bz, q0.z, q0.w)));
        float sB1 = fmaf(bx, q1.x, fmaf(by, q1.y, fmaf(bz, q1.z, q1.w)));
        float sB2 = fmaf(bx, q2.x, fmaf(by, q2.y, fmaf(bz, q2.z, q2.w)));
        float sB3 = fmaf(bx, q3.x, fmaf(by, q3.y, fmaf(bz, q3.z, q3.w)));
        float mA = fminf(fminf(sA0, sA1), fminf(sA2, sA3));
        float mB = fminf(fminf(sB0, sB1), fminf(sB2, sB3));
        if (mA < TA || mB < TB) {
            if (mA < TA) {
                float sv[UNR] = { sA0, sA1, sA2, sA3 };
#pragma unroll
                for (int u = 0; u < UNR; u++) {
                    if (sv[u] < tlA) {
                        float v = sv[u]; int ii = pbase + u * 32;
#pragma unroll
                        for (int j = 0; j < KSEL; j++) {
                            if (v < bestA[j]) {
                                float tv = bestA[j]; int ti = idxA[j];
                                bestA[j] = v; idxA[j] = ii;
                                v = tv; ii = ti;
                            }
                        }
                        tlA = bestA[KSEL - 1];
                    }
                }
                if (tlA < sTv[0]) sTv[0] = tlA;   // benign race: any stored value is a valid bound
            }
            if (mB < TB) {
                float sv[UNR] = { sB0, sB1, sB2, sB3 };
#pragma unroll
                for (int u = 0; u < UNR; u++) {
                    if (sv[u] < tlB) {
                        float v = sv[u]; int ii = pbase + u * 32;
#pragma unroll
                        for (int j = 0; j < KSEL; j++) {
                            if (v < bestB[j]) {
                                float tv = bestB[j]; int ti = idxB[j];
                                bestB[j] = v; idxB[j] = ii;
                                v = tv; ii = ti;
                            }
                        }
                        tlB = bestB[KSEL - 1];
                    }
                }
                if (tlB < sTv[1]) sTv[1] = tlB;
            }
        }
        p     += UNR * 32;
        pbase += UNR * 32;
    }
    // Tail: one point per lane (99968..99999), both rays
    {
        int k = NCHUNK * UNR * 32 + lane;
        float4 q = g_packed[k];
        float  sA = fmaf(ax, q.x, fmaf(ay, q.y, fmaf(az, q.z, q.w)));
        float  sB = fmaf(bx, q.x, fmaf(by, q.y, fmaf(bz, q.z, q.w)));
        if (sA < tlA) {
            float v = sA; int ii = k;
#pragma unroll
            for (int j = 0; j < KSEL; j++) {
                if (v < bestA[j]) {
                    float tv = bestA[j]; int ti = idxA[j];
                    bestA[j] = v; idxA[j] = ii; v = tv; ii = ti;
                }
            }
        }
        if (sB < tlB) {
            float v = sB; int ii = k;
#pragma unroll
            for (int j = 0; j < KSEL; j++) {
                if (v < bestB[j]) {
                    float tv = bestB[j]; int ti = idxB[j];
                    bestB[j] = v; idxB[j] = ii; v = tv; ii = ti;
                }
            }
        }
    }

    // Dump both lists (d^2 domain)
#pragma unroll
    for (int j = 0; j < KSEL; j++) {
        md2 [(0 * 32 + lane) * KSEL + j] = bestA[j] + CA;
        midx[(0 * 32 + lane) * KSEL + j] = idxA[j];
        md2 [(1 * 32 + lane) * KSEL + j] = bestB[j] + CB;
        midx[(1 * 32 + lane) * KSEL + j] = idxB[j];
    }

    // Merge 32 sorted lists -> 1 per ray (warp-local, lane mapped as rl=lane&1, sub=lane>>1)
    const int mrl = lane & 1;
    const int msb = lane >> 1;
    for (int stride = 16; stride >= 1; stride >>= 1) {
        __syncthreads();
        if (msb < stride) {
            int a = (mrl * 32 + msb) * KSEL;
            int b = (mrl * 32 + msb + stride) * KSEL;
            float ov[KSEL]; int oi[KSEL];
            int ia = 0, ib = 0;
#pragma unroll
            for (int k = 0; k < KSEL; k++) {
                float va = md2[a + ia], vb = md2[b + ib];
                if (va <= vb) { ov[k] = va; oi[k] = midx[a + ia]; ia++; }
                else          { ov[k] = vb; oi[k] = midx[b + ib]; ib++; }
            }
#pragma unroll
            for (int k = 0; k < KSEL; k++) { md2[a + k] = ov[k]; midx[a + k] = oi[k]; }
        }
    }
    __syncthreads();

    // Epilogue: lanes 0 and 1, one ray each
    if (lane < RPB) {
        int a = (lane * 32) * KSEL;
        float wsum = 0.f, r0 = 0.f, g0 = 0.f, b0 = 0.f;
#pragma unroll
        for (int k = 0; k < KSEL; k++) {
            float d2 = md2[a + k];
            int   ii = midx[a + k];
            float d  = sqrtf(fmaxf(d2, 0.0f));
            float op = 1.0f / (1.0f + expf(-opac[ii]));
            float w  = expf(-0.1f * d) * op;
            wsum += w;
            float c0 = 1.0f / (1.0f + expf(-fdc[ii * 3 + 0]));
            float c1 = 1.0f / (1.0f + expf(-fdc[ii * 3 + 1]));
            float c2 = 1.0f / (1.0f + expf(-fdc[ii * 3 + 2]));
            r0 = fmaf(w, c0, r0);
            g0 = fmaf(w, c1, g0);
            b0 = fmaf(w, c2, b0);
        }
        float inv = 1.0f / (wsum + 1e-8f);
        int ray = rayBase + lane;
        out[ray * 3 + 0] = r0 * inv;
        out[ray * 3 + 1] = g0 * inv;
        out[ray * 3 + 2] = b0 * inv;
    }
}

extern "C" void kernel_launch(void* const* d_in, const int* in_sizes, int n_in,
                              void* d_out, int out_size)
{
    const float* rays_o = (const float*)d_in[0];
    const float* rays_d = (const float*)d_in[1];
    const float* xyz    = (const float*)d_in[2];
    const float* fdc    = (const float*)d_in[3];
    const float* opac   = (const float*)d_in[4];
    float* out = (float*)d_out;

    pack_kernel<<<(NPTS + 255) / 256, 256>>>(xyz);
    gs_topk_kernel<<<GRID, TPB>>>(rays_o, rays_d, fdc, opac, out);
}